// round 1
// baseline (speedup 1.0000x reference)
#include <cuda_runtime.h>
#include <math.h>

#define B_    2
#define N_    1024
#define D_    1024
#define H_    16
#define DH_   64
#define MLP_  4096
#define DEPTH_ 6
#define M_    (B_ * N_)   /* 2048 rows */

// ---------------- scratch (static device globals; no runtime allocation) ----
__device__ float g_h   [(size_t)M_ * D_];          //  8 MB  LN output
__device__ float g_qkv [(size_t)M_ * 3 * D_];      // 24 MB  qkv projections
__device__ float g_attn[(size_t)B_ * H_ * N_ * N_];// 128 MB attention matrix
__device__ float g_o   [(size_t)M_ * D_];          //  8 MB  attention output
__device__ float g_mlp [(size_t)M_ * MLP_];        // 32 MB  MLP hidden

// ---------------- LayerNorm (one block per row, D=1024, 256 thr) ------------
__global__ void __launch_bounds__(256) ln_kernel(
    const float* __restrict__ x, const float* __restrict__ s,
    const float* __restrict__ b, float* __restrict__ o)
{
    __shared__ float red[2][8];
    int row = blockIdx.x;
    const float* xr = x + (size_t)row * D_;
    float* orow = o + (size_t)row * D_;
    int t = threadIdx.x;
    float v[4];
    float sum = 0.f, sq = 0.f;
#pragma unroll
    for (int i = 0; i < 4; i++) {
        float z = xr[t + i * 256];
        v[i] = z; sum += z; sq += z * z;
    }
#pragma unroll
    for (int off = 16; off > 0; off >>= 1) {
        sum += __shfl_xor_sync(0xffffffffu, sum, off);
        sq  += __shfl_xor_sync(0xffffffffu, sq,  off);
    }
    if ((t & 31) == 0) { red[0][t >> 5] = sum; red[1][t >> 5] = sq; }
    __syncthreads();
    sum = 0.f; sq = 0.f;
#pragma unroll
    for (int i = 0; i < 8; i++) { sum += red[0][i]; sq += red[1][i]; }
    float mean = sum * (1.f / D_);
    float var  = sq  * (1.f / D_) - mean * mean;
    float rstd = rsqrtf(var + 1e-5f);
#pragma unroll
    for (int i = 0; i < 4; i++) {
        int c = t + i * 256;
        orow[c] = (v[i] - mean) * rstd * s[c] + b[c];
    }
}

// ---------------- generic fp32 GEMM: C = A(MxK) * W(KxN) [+bias][gelu][+res]
// EPI bit0: +bias, bit1: gelu, bit2: +res. 128x128x16 tile, 8x8/thread.
template<int EPI>
__global__ void __launch_bounds__(256) gemm_kernel(
    const float* __restrict__ A, const float* __restrict__ W,
    const float* __restrict__ bias, const float* __restrict__ res,
    float* __restrict__ C, int M, int N, int K)
{
    const int BM = 128, BN = 128, BK = 16;
    __shared__ float As[BK][BM];
    __shared__ float Bs[BK][BN];
    int tid = threadIdx.x;
    int bx = blockIdx.x, by = blockIdx.y;
    const float* Ab = A + (size_t)by * BM * K;
    const float* Wb = W + (size_t)bx * BN;
    int ty = tid >> 4, tx = tid & 15;
    float acc[8][8];
#pragma unroll
    for (int i = 0; i < 8; i++)
#pragma unroll
        for (int j = 0; j < 8; j++) acc[i][j] = 0.f;

    for (int k0 = 0; k0 < K; k0 += BK) {
#pragma unroll
        for (int i = 0; i < 2; i++) {
            int l = tid + i * 256;              // 512 float4 per tile
            int ar = l >> 2, ac = (l & 3) * 4;  // A: 128 rows x 4 float4
            float4 fa = *(const float4*)(Ab + (size_t)ar * K + k0 + ac);
            As[ac + 0][ar] = fa.x; As[ac + 1][ar] = fa.y;
            As[ac + 2][ar] = fa.z; As[ac + 3][ar] = fa.w;
            int br = l >> 5, bc = (l & 31) * 4; // B: 16 rows x 32 float4
            *(float4*)(&Bs[br][bc]) =
                *(const float4*)(Wb + (size_t)(k0 + br) * N + bc);
        }
        __syncthreads();
#pragma unroll
        for (int kk = 0; kk < BK; kk++) {
            float a[8], bb[8];
            *(float4*)(a)      = *(const float4*)(&As[kk][ty * 8]);
            *(float4*)(a + 4)  = *(const float4*)(&As[kk][ty * 8 + 4]);
            *(float4*)(bb)     = *(const float4*)(&Bs[kk][tx * 8]);
            *(float4*)(bb + 4) = *(const float4*)(&Bs[kk][tx * 8 + 4]);
#pragma unroll
            for (int i = 0; i < 8; i++)
#pragma unroll
                for (int j = 0; j < 8; j++) acc[i][j] += a[i] * bb[j];
        }
        __syncthreads();
    }

    int r0 = by * BM + ty * 8;
    int c0 = bx * BN + tx * 8;
#pragma unroll
    for (int i = 0; i < 8; i++) {
        size_t base = (size_t)(r0 + i) * N + c0;
#pragma unroll
        for (int j = 0; j < 8; j++) {
            float v = acc[i][j];
            if (EPI & 1) v += bias[c0 + j];
            if (EPI & 2) v = 0.5f * v * (1.f + erff(v * 0.70710678118654752f));
            if (EPI & 4) v += res[base + j];
            C[base + j] = v;
        }
    }
}

// ---------------- attention scores: S = Q K^T * scale ----------------------
// grid (j_tile=16, i_tile=16, b*H=32); 64x64 tile, K=dh=64.
__global__ void __launch_bounds__(256) attn_scores_kernel(
    const float* __restrict__ qkv, float* __restrict__ attn)
{
    __shared__ float Qs[64][65];
    __shared__ float Ks[64][65];
    int bh = blockIdx.z;
    int b = bh >> 4, h = bh & 15;
    int i0 = blockIdx.y * 64, j0 = blockIdx.x * 64;
    const float* Qb = qkv + ((size_t)b * N_) * 3 * D_ + (size_t)h * DH_;
    int tid = threadIdx.x;
#pragma unroll
    for (int i = 0; i < 4; i++) {
        int l = tid + i * 256;              // 1024 float4 loads total
        int r = l >> 4, c = (l & 15) * 4;   // 64 rows x 16 float4
        float4 fq = *(const float4*)(Qb + (size_t)(i0 + r) * 3 * D_ + c);
        Qs[r][c] = fq.x; Qs[r][c+1] = fq.y; Qs[r][c+2] = fq.z; Qs[r][c+3] = fq.w;
        float4 fk = *(const float4*)(Qb + (size_t)(j0 + r) * 3 * D_ + D_ + c);
        Ks[r][c] = fk.x; Ks[r][c+1] = fk.y; Ks[r][c+2] = fk.z; Ks[r][c+3] = fk.w;
    }
    __syncthreads();
    int ty = tid >> 4, tx = tid & 15;
    float acc[4][4];
#pragma unroll
    for (int i = 0; i < 4; i++)
#pragma unroll
        for (int j = 0; j < 4; j++) acc[i][j] = 0.f;
#pragma unroll
    for (int d = 0; d < 64; d++) {
        float a[4], bb[4];
#pragma unroll
        for (int i = 0; i < 4; i++) a[i]  = Qs[ty * 4 + i][d];
#pragma unroll
        for (int j = 0; j < 4; j++) bb[j] = Ks[tx * 4 + j][d];
#pragma unroll
        for (int i = 0; i < 4; i++)
#pragma unroll
            for (int j = 0; j < 4; j++) acc[i][j] += a[i] * bb[j];
    }
    const float scale = 0.03125f;  // 1024^-0.5 (full-D scaling per reference)
    size_t base = ((size_t)bh * N_ + i0) * N_ + j0;
#pragma unroll
    for (int i = 0; i < 4; i++)
#pragma unroll
        for (int j = 0; j < 4; j++)
            attn[base + (size_t)(ty * 4 + i) * N_ + tx * 4 + j] = acc[i][j] * scale;
}

// ---------------- row softmax over N=1024 -----------------------------------
__global__ void __launch_bounds__(256) softmax_kernel(float* __restrict__ attn)
{
    __shared__ float red[8];
    size_t row = blockIdx.x;
    float* p = attn + row * N_;
    int t = threadIdx.x;
    float v[4];
    float mx = -1e30f;
#pragma unroll
    for (int i = 0; i < 4; i++) { v[i] = p[t + i * 256]; mx = fmaxf(mx, v[i]); }
#pragma unroll
    for (int off = 16; off > 0; off >>= 1)
        mx = fmaxf(mx, __shfl_xor_sync(0xffffffffu, mx, off));
    if ((t & 31) == 0) red[t >> 5] = mx;
    __syncthreads();
    mx = red[0];
#pragma unroll
    for (int i = 1; i < 8; i++) mx = fmaxf(mx, red[i]);
    __syncthreads();
    float sum = 0.f;
#pragma unroll
    for (int i = 0; i < 4; i++) { v[i] = __expf(v[i] - mx); sum += v[i]; }
#pragma unroll
    for (int off = 16; off > 0; off >>= 1)
        sum += __shfl_xor_sync(0xffffffffu, sum, off);
    if ((t & 31) == 0) red[t >> 5] = sum;
    __syncthreads();
    sum = 0.f;
#pragma unroll
    for (int i = 0; i < 8; i++) sum += red[i];
    float inv = 1.f / sum;
#pragma unroll
    for (int i = 0; i < 4; i++) p[t + i * 256] = v[i] * inv;
}

// ---------------- O = attn @ V, written back in [b, n, h*dh] layout ---------
// grid (i_tile=16, b*H=32); tile 64(i) x 64(d), K loop over j.
__global__ void __launch_bounds__(256) attn_av_kernel(
    const float* __restrict__ attn, const float* __restrict__ qkv,
    float* __restrict__ o)
{
    __shared__ float Ss[32][65];
    __shared__ float Vs[32][64];
    int bh = blockIdx.y;
    int b = bh >> 4, h = bh & 15;
    int i0 = blockIdx.x * 64;
    const float* Arow = attn + ((size_t)bh * N_ + i0) * N_;
    const float* Vb = qkv + ((size_t)b * N_) * 3 * D_ + 2 * D_ + (size_t)h * DH_;
    int tid = threadIdx.x;
    int ty = tid >> 4, tx = tid & 15;
    float acc[4][4];
#pragma unroll
    for (int i = 0; i < 4; i++)
#pragma unroll
        for (int j = 0; j < 4; j++) acc[i][j] = 0.f;

    for (int k0 = 0; k0 < N_; k0 += 32) {
#pragma unroll
        for (int i = 0; i < 2; i++) {
            int l = tid + i * 256;              // 512 float4 per tile
            int r = l >> 3, c = (l & 7) * 4;    // attn: 64 rows x 8 float4
            float4 fa = *(const float4*)(Arow + (size_t)r * N_ + k0 + c);
            Ss[c + 0][r] = fa.x; Ss[c + 1][r] = fa.y;
            Ss[c + 2][r] = fa.z; Ss[c + 3][r] = fa.w;
            int vr = l >> 4, vc = (l & 15) * 4; // V: 32 rows x 16 float4
            *(float4*)(&Vs[vr][vc]) =
                *(const float4*)(Vb + (size_t)(k0 + vr) * 3 * D_ + vc);
        }
        __syncthreads();
#pragma unroll
        for (int jj = 0; jj < 32; jj++) {
            float a[4], bb[4];
#pragma unroll
            for (int i = 0; i < 4; i++) a[i]  = Ss[jj][ty * 4 + i];
#pragma unroll
            for (int j = 0; j < 4; j++) bb[j] = Vs[jj][tx * 4 + j];
#pragma unroll
            for (int i = 0; i < 4; i++)
#pragma unroll
                for (int j = 0; j < 4; j++) acc[i][j] += a[i] * bb[j];
        }
        __syncthreads();
    }
#pragma unroll
    for (int i = 0; i < 4; i++) {
        size_t base = ((size_t)b * N_ + i0 + ty * 4 + i) * D_ + (size_t)h * DH_ + tx * 4;
#pragma unroll
        for (int j = 0; j < 4; j++) o[base + j] = acc[i][j];
    }
}

// ---------------- orchestration ---------------------------------------------
extern "C" void kernel_launch(void* const* d_in, const int* in_sizes, int n_in,
                              void* d_out, int out_size)
{
    (void)in_sizes; (void)n_in; (void)out_size;
    const float* x     = (const float*)d_in[0];
    const float* ln1_s = (const float*)d_in[1];
    const float* ln1_b = (const float*)d_in[2];
    const float* w_qkv = (const float*)d_in[3];
    const float* w_out = (const float*)d_in[4];
    const float* b_out = (const float*)d_in[5];
    const float* ln2_s = (const float*)d_in[6];
    const float* ln2_b = (const float*)d_in[7];
    const float* w1    = (const float*)d_in[8];
    const float* b1    = (const float*)d_in[9];
    const float* w2    = (const float*)d_in[10];
    const float* b2    = (const float*)d_in[11];
    float* out = (float*)d_out;

    float *h, *qkv, *attn, *o, *mlp;
    cudaGetSymbolAddress((void**)&h,    g_h);
    cudaGetSymbolAddress((void**)&qkv,  g_qkv);
    cudaGetSymbolAddress((void**)&attn, g_attn);
    cudaGetSymbolAddress((void**)&o,    g_o);
    cudaGetSymbolAddress((void**)&mlp,  g_mlp);

    // x lives in d_out across layers (residual stream)
    cudaMemcpyAsync(out, x, (size_t)M_ * D_ * sizeof(float),
                    cudaMemcpyDeviceToDevice);

    for (int l = 0; l < DEPTH_; l++) {
        // --- attention block ---
        ln_kernel<<<M_, 256>>>(out, ln1_s + (size_t)l * D_, ln1_b + (size_t)l * D_, h);
        gemm_kernel<0><<<dim3(3 * D_ / 128, M_ / 128), 256>>>(
            h, w_qkv + (size_t)l * D_ * 3 * D_, nullptr, nullptr,
            qkv, M_, 3 * D_, D_);
        attn_scores_kernel<<<dim3(16, 16, B_ * H_), 256>>>(qkv, attn);
        softmax_kernel<<<B_ * H_ * N_, 256>>>(attn);
        attn_av_kernel<<<dim3(16, B_ * H_), 256>>>(attn, qkv, o);
        gemm_kernel<5><<<dim3(D_ / 128, M_ / 128), 256>>>(
            o, w_out + (size_t)l * D_ * D_, b_out + (size_t)l * D_,
            out, out, M_, D_, D_);
        // --- MLP block ---
        ln_kernel<<<M_, 256>>>(out, ln2_s + (size_t)l * D_, ln2_b + (size_t)l * D_, h);
        gemm_kernel<3><<<dim3(MLP_ / 128, M_ / 128), 256>>>(
            h, w1 + (size_t)l * D_ * MLP_, b1 + (size_t)l * MLP_,
            nullptr, mlp, M_, MLP_, D_);
        gemm_kernel<5><<<dim3(D_ / 128, M_ / 128), 256>>>(
            mlp, w2 + (size_t)l * MLP_ * D_, b2 + (size_t)l * D_,
            out, out, M_, D_, MLP_);
    }
}

// round 2
// speedup vs baseline: 2.3930x; 2.3930x over previous
#include <cuda_runtime.h>
#include <math.h>
#include <stdint.h>

#define B_    2
#define N_    1024
#define D_    1024
#define H_    16
#define DH_   64
#define MLP_  4096
#define DEPTH_ 6
#define M_    (B_ * N_)   /* 2048 rows */

// ---------------- scratch -----------------------------------------------
__device__ float g_h   [(size_t)M_ * D_];
__device__ float g_qkv [(size_t)M_ * 3 * D_];
__device__ float g_attn[(size_t)B_ * H_ * N_ * N_];
__device__ float g_o   [(size_t)M_ * D_];
__device__ float g_mlp [(size_t)M_ * MLP_];

// ---------------- tf32 helpers ------------------------------------------
__device__ __forceinline__ float f2tf(float x) {
    uint32_t u; asm("cvt.rna.tf32.f32 %0, %1;" : "=r"(u) : "f"(x));
    return __uint_as_float(u);
}
// D += A(16x8) * B(8x8), tf32, fp32 accum
__device__ __forceinline__ void mma8(float* d, const float* a, const float* b) {
    asm volatile(
        "mma.sync.aligned.m16n8k8.row.col.f32.tf32.tf32.f32 "
        "{%0,%1,%2,%3},{%4,%5,%6,%7},{%8,%9},{%0,%1,%2,%3};"
        : "+f"(d[0]), "+f"(d[1]), "+f"(d[2]), "+f"(d[3])
        : "r"(__float_as_uint(a[0])), "r"(__float_as_uint(a[1])),
          "r"(__float_as_uint(a[2])), "r"(__float_as_uint(a[3])),
          "r"(__float_as_uint(b[0])), "r"(__float_as_uint(b[1])));
}

// ---------------- LayerNorm ----------------------------------------------
__global__ void __launch_bounds__(256) ln_kernel(
    const float* __restrict__ x, const float* __restrict__ s,
    const float* __restrict__ b, float* __restrict__ o)
{
    __shared__ float red[2][8];
    int row = blockIdx.x;
    const float* xr = x + (size_t)row * D_;
    float* orow = o + (size_t)row * D_;
    int t = threadIdx.x;
    float v[4];
    float sum = 0.f, sq = 0.f;
#pragma unroll
    for (int i = 0; i < 4; i++) {
        float z = xr[t + i * 256];
        v[i] = z; sum += z; sq += z * z;
    }
#pragma unroll
    for (int off = 16; off > 0; off >>= 1) {
        sum += __shfl_xor_sync(0xffffffffu, sum, off);
        sq  += __shfl_xor_sync(0xffffffffu, sq,  off);
    }
    if ((t & 31) == 0) { red[0][t >> 5] = sum; red[1][t >> 5] = sq; }
    __syncthreads();
    sum = 0.f; sq = 0.f;
#pragma unroll
    for (int i = 0; i < 8; i++) { sum += red[0][i]; sq += red[1][i]; }
    float mean = sum * (1.f / D_);
    float var  = sq  * (1.f / D_) - mean * mean;
    float rstd = rsqrtf(var + 1e-5f);
#pragma unroll
    for (int i = 0; i < 4; i++) {
        int c = t + i * 256;
        orow[c] = (v[i] - mean) * rstd * s[c] + b[c];
    }
}

// ---------------- tf32 tensor-core GEMM ----------------------------------
// C(MxN) = A(MxK) * W(KxN).  EPI bit0:+bias bit1:gelu bit2:+res
// 128x128 tile, BK=32, 256 thr = 8 warps (4m x 2n), warp tile 32x64.
template<int EPI>
__global__ void __launch_bounds__(256) gemm_tc(
    const float* __restrict__ A, const float* __restrict__ W,
    const float* __restrict__ bias, const float* __restrict__ res,
    float* __restrict__ C, int M, int N, int K)
{
    __shared__ float As[128][36];   // [m][k]
    __shared__ float Bs[32][132];   // [k][n]
    int tid = threadIdx.x;
    int bx = blockIdx.x, by = blockIdx.y;
    int w = tid >> 5, lane = tid & 31;
    int wm = w >> 1, wn = w & 1;
    int g = lane >> 2, q = lane & 3;

    float acc[2][8][4];
#pragma unroll
    for (int mi = 0; mi < 2; mi++)
#pragma unroll
        for (int ni = 0; ni < 8; ni++)
#pragma unroll
            for (int k = 0; k < 4; k++) acc[mi][ni][k] = 0.f;

    for (int k0 = 0; k0 < K; k0 += 32) {
#pragma unroll
        for (int i = 0; i < 4; i++) {
            int idx = tid + i * 256;
            int r = idx >> 3, c4 = (idx & 7) * 4;
            float4 f = *(const float4*)(A + (size_t)(by * 128 + r) * K + k0 + c4);
            f.x = f2tf(f.x); f.y = f2tf(f.y); f.z = f2tf(f.z); f.w = f2tf(f.w);
            *(float4*)&As[r][c4] = f;
        }
#pragma unroll
        for (int i = 0; i < 4; i++) {
            int idx = tid + i * 256;
            int r = idx >> 5, c4 = (idx & 31) * 4;
            float4 f = *(const float4*)(W + (size_t)(k0 + r) * N + bx * 128 + c4);
            f.x = f2tf(f.x); f.y = f2tf(f.y); f.z = f2tf(f.z); f.w = f2tf(f.w);
            *(float4*)&Bs[r][c4] = f;
        }
        __syncthreads();
#pragma unroll
        for (int ks = 0; ks < 4; ks++) {
            int kb = ks * 8;
            float a[2][4];
#pragma unroll
            for (int mi = 0; mi < 2; mi++) {
                int m = wm * 32 + mi * 16;
                a[mi][0] = As[m + g    ][kb + q];
                a[mi][1] = As[m + g + 8][kb + q];
                a[mi][2] = As[m + g    ][kb + q + 4];
                a[mi][3] = As[m + g + 8][kb + q + 4];
            }
            float b[8][2];
#pragma unroll
            for (int ni = 0; ni < 8; ni++) {
                int n = wn * 64 + ni * 8 + g;
                b[ni][0] = Bs[kb + q    ][n];
                b[ni][1] = Bs[kb + q + 4][n];
            }
#pragma unroll
            for (int mi = 0; mi < 2; mi++)
#pragma unroll
                for (int ni = 0; ni < 8; ni++) mma8(acc[mi][ni], a[mi], b[ni]);
        }
        __syncthreads();
    }

#pragma unroll
    for (int mi = 0; mi < 2; mi++) {
        int r0 = by * 128 + wm * 32 + mi * 16 + g;
#pragma unroll
        for (int ni = 0; ni < 8; ni++) {
            int c = bx * 128 + wn * 64 + ni * 8 + q * 2;
            float2 v0 = make_float2(acc[mi][ni][0], acc[mi][ni][1]); // row r0
            float2 v1 = make_float2(acc[mi][ni][2], acc[mi][ni][3]); // row r0+8
            if (EPI & 1) {
                float b0 = bias[c], b1 = bias[c + 1];
                v0.x += b0; v0.y += b1; v1.x += b0; v1.y += b1;
            }
            if (EPI & 2) {
                const float is2 = 0.70710678118654752f;
                v0.x = 0.5f * v0.x * (1.f + erff(v0.x * is2));
                v0.y = 0.5f * v0.y * (1.f + erff(v0.y * is2));
                v1.x = 0.5f * v1.x * (1.f + erff(v1.x * is2));
                v1.y = 0.5f * v1.y * (1.f + erff(v1.y * is2));
            }
            size_t a0 = (size_t)r0 * N + c;
            size_t a1 = (size_t)(r0 + 8) * N + c;
            if (EPI & 4) {
                float2 r0v = *(const float2*)(res + a0);
                float2 r1v = *(const float2*)(res + a1);
                v0.x += r0v.x; v0.y += r0v.y; v1.x += r1v.x; v1.y += r1v.y;
            }
            *(float2*)(C + a0) = v0;
            *(float2*)(C + a1) = v1;
        }
    }
}

// ---------------- attention scores: S = Q K^T * scale (tf32 TC) -----------
// grid(x=j_tile 8, y=i_tile 8, z=bh 32). 128x128 tile, K=64 in 2 chunks.
__global__ void __launch_bounds__(256) scores_tc(
    const float* __restrict__ qkv, float* __restrict__ attn)
{
    __shared__ float Qs[128][36];   // [i][d]
    __shared__ float Ks[128][36];   // [j][d]
    int bh = blockIdx.z;
    int b = bh >> 4, h = bh & 15;
    int i0 = blockIdx.y * 128, j0 = blockIdx.x * 128;
    const float* Qb = qkv + (size_t)b * N_ * 3 * D_ + (size_t)h * DH_;
    const float* Kb = Qb + D_;
    int tid = threadIdx.x;
    int w = tid >> 5, lane = tid & 31;
    int wm = w >> 1, wn = w & 1;
    int g = lane >> 2, q = lane & 3;

    float acc[2][8][4];
#pragma unroll
    for (int mi = 0; mi < 2; mi++)
#pragma unroll
        for (int ni = 0; ni < 8; ni++)
#pragma unroll
            for (int k = 0; k < 4; k++) acc[mi][ni][k] = 0.f;

#pragma unroll
    for (int k0 = 0; k0 < 64; k0 += 32) {
#pragma unroll
        for (int i = 0; i < 4; i++) {
            int idx = tid + i * 256;
            int r = idx >> 3, c4 = (idx & 7) * 4;
            float4 fq = *(const float4*)(Qb + (size_t)(i0 + r) * 3 * D_ + k0 + c4);
            fq.x = f2tf(fq.x); fq.y = f2tf(fq.y); fq.z = f2tf(fq.z); fq.w = f2tf(fq.w);
            *(float4*)&Qs[r][c4] = fq;
            float4 fk = *(const float4*)(Kb + (size_t)(j0 + r) * 3 * D_ + k0 + c4);
            fk.x = f2tf(fk.x); fk.y = f2tf(fk.y); fk.z = f2tf(fk.z); fk.w = f2tf(fk.w);
            *(float4*)&Ks[r][c4] = fk;
        }
        __syncthreads();
#pragma unroll
        for (int ks = 0; ks < 4; ks++) {
            int kb = ks * 8;
            float a[2][4];
#pragma unroll
            for (int mi = 0; mi < 2; mi++) {
                int m = wm * 32 + mi * 16;
                a[mi][0] = Qs[m + g    ][kb + q];
                a[mi][1] = Qs[m + g + 8][kb + q];
                a[mi][2] = Qs[m + g    ][kb + q + 4];
                a[mi][3] = Qs[m + g + 8][kb + q + 4];
            }
            float bf[8][2];
#pragma unroll
            for (int ni = 0; ni < 8; ni++) {
                int n = wn * 64 + ni * 8 + g;
                bf[ni][0] = Ks[n][kb + q];
                bf[ni][1] = Ks[n][kb + q + 4];
            }
#pragma unroll
            for (int mi = 0; mi < 2; mi++)
#pragma unroll
                for (int ni = 0; ni < 8; ni++) mma8(acc[mi][ni], a[mi], bf[ni]);
        }
        __syncthreads();
    }

    const float scale = 0.03125f;   // D^-0.5 (full-dim per reference)
#pragma unroll
    for (int mi = 0; mi < 2; mi++) {
        int r0 = i0 + wm * 32 + mi * 16 + g;
#pragma unroll
        for (int ni = 0; ni < 8; ni++) {
            int c = j0 + wn * 64 + ni * 8 + q * 2;
            size_t a0 = ((size_t)bh * N_ + r0) * N_ + c;
            size_t a1 = ((size_t)bh * N_ + r0 + 8) * N_ + c;
            *(float2*)(attn + a0) =
                make_float2(acc[mi][ni][0] * scale, acc[mi][ni][1] * scale);
            *(float2*)(attn + a1) =
                make_float2(acc[mi][ni][2] * scale, acc[mi][ni][3] * scale);
        }
    }
}

// ---------------- row softmax over N=1024 ----------------------------------
__global__ void __launch_bounds__(256) softmax_kernel(float* __restrict__ attn)
{
    __shared__ float red[8];
    size_t row = blockIdx.x;
    float* p = attn + row * N_;
    int t = threadIdx.x;
    float v[4];
    float mx = -1e30f;
#pragma unroll
    for (int i = 0; i < 4; i++) { v[i] = p[t + i * 256]; mx = fmaxf(mx, v[i]); }
#pragma unroll
    for (int off = 16; off > 0; off >>= 1)
        mx = fmaxf(mx, __shfl_xor_sync(0xffffffffu, mx, off));
    if ((t & 31) == 0) red[t >> 5] = mx;
    __syncthreads();
    mx = red[0];
#pragma unroll
    for (int i = 1; i < 8; i++) mx = fmaxf(mx, red[i]);
    __syncthreads();
    float sum = 0.f;
#pragma unroll
    for (int i = 0; i < 4; i++) { v[i] = __expf(v[i] - mx); sum += v[i]; }
#pragma unroll
    for (int off = 16; off > 0; off >>= 1)
        sum += __shfl_xor_sync(0xffffffffu, sum, off);
    if ((t & 31) == 0) red[t >> 5] = sum;
    __syncthreads();
    sum = 0.f;
#pragma unroll
    for (int i = 0; i < 8; i++) sum += red[i];
    float inv = 1.f / sum;
#pragma unroll
    for (int i = 0; i < 4; i++) p[t + i * 256] = v[i] * inv;
}

// ---------------- O = attn @ V (tf32 TC), output [b, n, h*dh] --------------
// grid(x=i_tile 8, y=bh 32). Tile 128(i) x 64(d), BK=32 over j.
__global__ void __launch_bounds__(256) av_tc(
    const float* __restrict__ attn, const float* __restrict__ qkv,
    float* __restrict__ o)
{
    __shared__ float As[128][36];   // [i][j]
    __shared__ float Vs[32][68];    // [j][d]
    int bh = blockIdx.y;
    int b = bh >> 4, h = bh & 15;
    int i0 = blockIdx.x * 128;
    const float* Ab = attn + ((size_t)bh * N_ + i0) * N_;
    const float* Vb = qkv + (size_t)b * N_ * 3 * D_ + 2 * D_ + (size_t)h * DH_;
    int tid = threadIdx.x;
    int w = tid >> 5, lane = tid & 31;
    int wm = w >> 1, wn = w & 1;
    int g = lane >> 2, q = lane & 3;

    float acc[2][4][4];
#pragma unroll
    for (int mi = 0; mi < 2; mi++)
#pragma unroll
        for (int ni = 0; ni < 4; ni++)
#pragma unroll
            for (int k = 0; k < 4; k++) acc[mi][ni][k] = 0.f;

    for (int k0 = 0; k0 < N_; k0 += 32) {
#pragma unroll
        for (int i = 0; i < 4; i++) {
            int idx = tid + i * 256;
            int r = idx >> 3, c4 = (idx & 7) * 4;
            float4 f = *(const float4*)(Ab + (size_t)r * N_ + k0 + c4);
            f.x = f2tf(f.x); f.y = f2tf(f.y); f.z = f2tf(f.z); f.w = f2tf(f.w);
            *(float4*)&As[r][c4] = f;
        }
#pragma unroll
        for (int i = 0; i < 2; i++) {
            int idx = tid + i * 256;
            int r = idx >> 4, c4 = (idx & 15) * 4;
            float4 f = *(const float4*)(Vb + (size_t)(k0 + r) * 3 * D_ + c4);
            f.x = f2tf(f.x); f.y = f2tf(f.y); f.z = f2tf(f.z); f.w = f2tf(f.w);
            *(float4*)&Vs[r][c4] = f;
        }
        __syncthreads();
#pragma unroll
        for (int ks = 0; ks < 4; ks++) {
            int kb = ks * 8;
            float a[2][4];
#pragma unroll
            for (int mi = 0; mi < 2; mi++) {
                int m = wm * 32 + mi * 16;
                a[mi][0] = As[m + g    ][kb + q];
                a[mi][1] = As[m + g + 8][kb + q];
                a[mi][2] = As[m + g    ][kb + q + 4];
                a[mi][3] = As[m + g + 8][kb + q + 4];
            }
            float bf[4][2];
#pragma unroll
            for (int ni = 0; ni < 4; ni++) {
                int n = wn * 32 + ni * 8 + g;
                bf[ni][0] = Vs[kb + q    ][n];
                bf[ni][1] = Vs[kb + q + 4][n];
            }
#pragma unroll
            for (int mi = 0; mi < 2; mi++)
#pragma unroll
                for (int ni = 0; ni < 4; ni++) mma8(acc[mi][ni], a[mi], bf[ni]);
        }
        __syncthreads();
    }

#pragma unroll
    for (int mi = 0; mi < 2; mi++) {
        int r0 = i0 + wm * 32 + mi * 16 + g;
#pragma unroll
        for (int ni = 0; ni < 4; ni++) {
            int c = wn * 32 + ni * 8 + q * 2;
            size_t a0 = ((size_t)b * N_ + r0) * D_ + h * DH_ + c;
            size_t a1 = ((size_t)b * N_ + r0 + 8) * D_ + h * DH_ + c;
            *(float2*)(o + a0) = make_float2(acc[mi][ni][0], acc[mi][ni][1]);
            *(float2*)(o + a1) = make_float2(acc[mi][ni][2], acc[mi][ni][3]);
        }
    }
}

// ---------------- orchestration --------------------------------------------
extern "C" void kernel_launch(void* const* d_in, const int* in_sizes, int n_in,
                              void* d_out, int out_size)
{
    (void)in_sizes; (void)n_in; (void)out_size;
    const float* x     = (const float*)d_in[0];
    const float* ln1_s = (const float*)d_in[1];
    const float* ln1_b = (const float*)d_in[2];
    const float* w_qkv = (const float*)d_in[3];
    const float* w_out = (const float*)d_in[4];
    const float* b_out = (const float*)d_in[5];
    const float* ln2_s = (const float*)d_in[6];
    const float* ln2_b = (const float*)d_in[7];
    const float* w1    = (const float*)d_in[8];
    const float* b1    = (const float*)d_in[9];
    const float* w2    = (const float*)d_in[10];
    const float* b2    = (const float*)d_in[11];
    float* out = (float*)d_out;

    float *h, *qkv, *attn, *o, *mlp;
    cudaGetSymbolAddress((void**)&h,    g_h);
    cudaGetSymbolAddress((void**)&qkv,  g_qkv);
    cudaGetSymbolAddress((void**)&attn, g_attn);
    cudaGetSymbolAddress((void**)&o,    g_o);
    cudaGetSymbolAddress((void**)&mlp,  g_mlp);

    cudaMemcpyAsync(out, x, (size_t)M_ * D_ * sizeof(float),
                    cudaMemcpyDeviceToDevice);

    for (int l = 0; l < DEPTH_; l++) {
        // --- attention block ---
        ln_kernel<<<M_, 256>>>(out, ln1_s + (size_t)l * D_, ln1_b + (size_t)l * D_, h);
        gemm_tc<0><<<dim3(3 * D_ / 128, M_ / 128), 256>>>(
            h, w_qkv + (size_t)l * D_ * 3 * D_, nullptr, nullptr,
            qkv, M_, 3 * D_, D_);
        scores_tc<<<dim3(8, 8, B_ * H_), 256>>>(qkv, attn);
        softmax_kernel<<<B_ * H_ * N_, 256>>>(attn);
        av_tc<<<dim3(8, B_ * H_), 256>>>(attn, qkv, o);
        gemm_tc<5><<<dim3(D_ / 128, M_ / 128), 256>>>(
            o, w_out + (size_t)l * D_ * D_, b_out + (size_t)l * D_,
            out, out, M_, D_, D_);
        // --- MLP block ---
        ln_kernel<<<M_, 256>>>(out, ln2_s + (size_t)l * D_, ln2_b + (size_t)l * D_, h);
        gemm_tc<3><<<dim3(MLP_ / 128, M_ / 128), 256>>>(
            h, w1 + (size_t)l * D_ * MLP_, b1 + (size_t)l * MLP_,
            nullptr, mlp, M_, MLP_, D_);
        gemm_tc<5><<<dim3(D_ / 128, M_ / 128), 256>>>(
            mlp, w2 + (size_t)l * MLP_ * D_, b2 + (size_t)l * D_,
            out, out, M_, D_, MLP_);
    }
}

// round 3
// speedup vs baseline: 2.7155x; 1.1348x over previous
#include <cuda_runtime.h>
#include <math.h>
#include <stdint.h>

#define B_    2
#define N_    1024
#define D_    1024
#define H_    16
#define DH_   64
#define MLP_  4096
#define DEPTH_ 6
#define M_    (B_ * N_)   /* 2048 rows */

// ---------------- scratch -----------------------------------------------
__device__ float g_h   [(size_t)M_ * D_];
__device__ float g_qkv [(size_t)M_ * 3 * D_];
__device__ float g_attn[(size_t)B_ * H_ * N_ * N_];
__device__ float g_o   [(size_t)M_ * D_];
__device__ float g_mlp [(size_t)M_ * MLP_];

// ---------------- tf32 / async helpers ------------------------------------
__device__ __forceinline__ float f2tf(float x) {
    uint32_t u; asm("cvt.rna.tf32.f32 %0, %1;" : "=r"(u) : "f"(x));
    return __uint_as_float(u);
}
__device__ __forceinline__ void mma8(float* d, const float* a, const float* b) {
    asm volatile(
        "mma.sync.aligned.m16n8k8.row.col.f32.tf32.tf32.f32 "
        "{%0,%1,%2,%3},{%4,%5,%6,%7},{%8,%9},{%0,%1,%2,%3};"
        : "+f"(d[0]), "+f"(d[1]), "+f"(d[2]), "+f"(d[3])
        : "r"(__float_as_uint(a[0])), "r"(__float_as_uint(a[1])),
          "r"(__float_as_uint(a[2])), "r"(__float_as_uint(a[3])),
          "r"(__float_as_uint(b[0])), "r"(__float_as_uint(b[1])));
}
__device__ __forceinline__ void cp16(void* smem_dst, const void* gmem_src) {
    uint32_t dst = (uint32_t)__cvta_generic_to_shared(smem_dst);
    asm volatile("cp.async.cg.shared.global [%0], [%1], 16;"
                 :: "r"(dst), "l"(gmem_src));
}
__device__ __forceinline__ void cp_commit() {
    asm volatile("cp.async.commit_group;");
}

// ---------------- LayerNorm ----------------------------------------------
__global__ void __launch_bounds__(256) ln_kernel(
    const float* __restrict__ x, const float* __restrict__ s,
    const float* __restrict__ b, float* __restrict__ o)
{
    __shared__ float red[2][8];
    int row = blockIdx.x;
    const float* xr = x + (size_t)row * D_;
    float* orow = o + (size_t)row * D_;
    int t = threadIdx.x;
    float v[4];
    float sum = 0.f, sq = 0.f;
#pragma unroll
    for (int i = 0; i < 4; i++) {
        float z = xr[t + i * 256];
        v[i] = z; sum += z; sq += z * z;
    }
#pragma unroll
    for (int off = 16; off > 0; off >>= 1) {
        sum += __shfl_xor_sync(0xffffffffu, sum, off);
        sq  += __shfl_xor_sync(0xffffffffu, sq,  off);
    }
    if ((t & 31) == 0) { red[0][t >> 5] = sum; red[1][t >> 5] = sq; }
    __syncthreads();
    sum = 0.f; sq = 0.f;
#pragma unroll
    for (int i = 0; i < 8; i++) { sum += red[0][i]; sq += red[1][i]; }
    float mean = sum * (1.f / D_);
    float var  = sq  * (1.f / D_) - mean * mean;
    float rstd = rsqrtf(var + 1e-5f);
#pragma unroll
    for (int i = 0; i < 4; i++) {
        int c = t + i * 256;
        orow[c] = (v[i] - mean) * rstd * s[c] + b[c];
    }
}

// ---------------- tf32 tensor-core GEMM, cp.async double-buffered ----------
// C(MxN) = A(MxK) * W(KxN).  EPI bit0:+bias bit1:gelu bit2:+res
// BM=128, BK=32, 256 threads (8 warps). Warp tile WM x WN.
// BN=256: WM=64 WN=64 (warps 2x4).  BN=128: WM=32 WN=64 (warps 4x2).
template<int BN, int WM, int WN, int EPI>
__global__ void __launch_bounds__(256, 1) gemm_tc(
    const float* __restrict__ A, const float* __restrict__ W,
    const float* __restrict__ bias, const float* __restrict__ res,
    float* __restrict__ C, int M, int N, int K)
{
    const int BNP = BN + 4;
    const int MI = WM / 16, NI = WN / 8;
    const int WARPS_N = BN / WN;

    extern __shared__ float sm[];
    float (*As)[128][36] = reinterpret_cast<float(*)[128][36]>(sm);
    float (*Bs)[32][BNP] = reinterpret_cast<float(*)[32][BNP]>(sm + 2 * 128 * 36);

    int tid = threadIdx.x;
    int bx = blockIdx.x, by = blockIdx.y;
    int w = tid >> 5, lane = tid & 31;
    int wn = w % WARPS_N, wm = w / WARPS_N;
    int g = lane >> 2, q = lane & 3;

    const float* Ab = A + (size_t)by * 128 * K;
    const float* Wb = W + (size_t)bx * BN;
    int KT = K / 32;

    float acc[MI][NI][4];
#pragma unroll
    for (int mi = 0; mi < MI; mi++)
#pragma unroll
        for (int ni = 0; ni < NI; ni++)
#pragma unroll
            for (int k = 0; k < 4; k++) acc[mi][ni][k] = 0.f;

    auto load_tile = [&](int kt, int s) {
        int k0 = kt * 32;
#pragma unroll
        for (int i = 0; i < 4; i++) {                 // A: 128x32
            int idx = tid + i * 256;
            int r = idx >> 3, c4 = (idx & 7) * 4;
            cp16(&As[s][r][c4], Ab + (size_t)r * K + k0 + c4);
        }
#pragma unroll
        for (int i = 0; i < BN / 32; i++) {           // B: 32xBN
            int idx = tid + i * 256;
            int r = idx / (BN / 4), c4 = (idx % (BN / 4)) * 4;
            cp16(&Bs[s][r][c4], Wb + (size_t)(k0 + r) * N + c4);
        }
        cp_commit();
    };

    load_tile(0, 0);

    for (int kt = 0; kt < KT; kt++) {
        int s = kt & 1;
        if (kt + 1 < KT) {
            load_tile(kt + 1, (kt + 1) & 1);
            asm volatile("cp.async.wait_group 1;");
        } else {
            asm volatile("cp.async.wait_group 0;");
        }
        __syncthreads();
#pragma unroll
        for (int ks = 0; ks < 4; ks++) {
            int kb = ks * 8;
            float a[MI][4];
#pragma unroll
            for (int mi = 0; mi < MI; mi++) {
                int m = wm * WM + mi * 16;
                a[mi][0] = f2tf(As[s][m + g    ][kb + q]);
                a[mi][1] = f2tf(As[s][m + g + 8][kb + q]);
                a[mi][2] = f2tf(As[s][m + g    ][kb + q + 4]);
                a[mi][3] = f2tf(As[s][m + g + 8][kb + q + 4]);
            }
            float b[NI][2];
#pragma unroll
            for (int ni = 0; ni < NI; ni++) {
                int n = wn * WN + ni * 8 + g;
                b[ni][0] = f2tf(Bs[s][kb + q    ][n]);
                b[ni][1] = f2tf(Bs[s][kb + q + 4][n]);
            }
#pragma unroll
            for (int mi = 0; mi < MI; mi++)
#pragma unroll
                for (int ni = 0; ni < NI; ni++) mma8(acc[mi][ni], a[mi], b[ni]);
        }
        __syncthreads();
    }

#pragma unroll
    for (int mi = 0; mi < MI; mi++) {
        int r0 = by * 128 + wm * WM + mi * 16 + g;
#pragma unroll
        for (int ni = 0; ni < NI; ni++) {
            int c = bx * BN + wn * WN + ni * 8 + q * 2;
            float2 v0 = make_float2(acc[mi][ni][0], acc[mi][ni][1]);
            float2 v1 = make_float2(acc[mi][ni][2], acc[mi][ni][3]);
            if (EPI & 1) {
                float b0 = bias[c], b1 = bias[c + 1];
                v0.x += b0; v0.y += b1; v1.x += b0; v1.y += b1;
            }
            if (EPI & 2) {
                const float is2 = 0.70710678118654752f;
                v0.x = 0.5f * v0.x * (1.f + erff(v0.x * is2));
                v0.y = 0.5f * v0.y * (1.f + erff(v0.y * is2));
                v1.x = 0.5f * v1.x * (1.f + erff(v1.x * is2));
                v1.y = 0.5f * v1.y * (1.f + erff(v1.y * is2));
            }
            size_t a0 = (size_t)r0 * N + c;
            size_t a1 = (size_t)(r0 + 8) * N + c;
            if (EPI & 4) {
                float2 r0v = *(const float2*)(res + a0);
                float2 r1v = *(const float2*)(res + a1);
                v0.x += r0v.x; v0.y += r0v.y; v1.x += r1v.x; v1.y += r1v.y;
            }
            *(float2*)(C + a0) = v0;
            *(float2*)(C + a1) = v1;
        }
    }
}

// ---------------- attention scores: S = Q K^T * scale (tf32 TC) -----------
__global__ void __launch_bounds__(256) scores_tc(
    const float* __restrict__ qkv, float* __restrict__ attn)
{
    __shared__ float Qs[128][36];
    __shared__ float Ks[128][36];
    int bh = blockIdx.z;
    int b = bh >> 4, h = bh & 15;
    int i0 = blockIdx.y * 128, j0 = blockIdx.x * 128;
    const float* Qb = qkv + (size_t)b * N_ * 3 * D_ + (size_t)h * DH_;
    const float* Kb = Qb + D_;
    int tid = threadIdx.x;
    int w = tid >> 5, lane = tid & 31;
    int wm = w >> 1, wn = w & 1;
    int g = lane >> 2, q = lane & 3;

    float acc[2][8][4];
#pragma unroll
    for (int mi = 0; mi < 2; mi++)
#pragma unroll
        for (int ni = 0; ni < 8; ni++)
#pragma unroll
            for (int k = 0; k < 4; k++) acc[mi][ni][k] = 0.f;

#pragma unroll
    for (int k0 = 0; k0 < 64; k0 += 32) {
#pragma unroll
        for (int i = 0; i < 4; i++) {
            int idx = tid + i * 256;
            int r = idx >> 3, c4 = (idx & 7) * 4;
            float4 fq = *(const float4*)(Qb + (size_t)(i0 + r) * 3 * D_ + k0 + c4);
            fq.x = f2tf(fq.x); fq.y = f2tf(fq.y); fq.z = f2tf(fq.z); fq.w = f2tf(fq.w);
            *(float4*)&Qs[r][c4] = fq;
            float4 fk = *(const float4*)(Kb + (size_t)(j0 + r) * 3 * D_ + k0 + c4);
            fk.x = f2tf(fk.x); fk.y = f2tf(fk.y); fk.z = f2tf(fk.z); fk.w = f2tf(fk.w);
            *(float4*)&Ks[r][c4] = fk;
        }
        __syncthreads();
#pragma unroll
        for (int ks = 0; ks < 4; ks++) {
            int kb = ks * 8;
            float a[2][4];
#pragma unroll
            for (int mi = 0; mi < 2; mi++) {
                int m = wm * 32 + mi * 16;
                a[mi][0] = Qs[m + g    ][kb + q];
                a[mi][1] = Qs[m + g + 8][kb + q];
                a[mi][2] = Qs[m + g    ][kb + q + 4];
                a[mi][3] = Qs[m + g + 8][kb + q + 4];
            }
            float bf[8][2];
#pragma unroll
            for (int ni = 0; ni < 8; ni++) {
                int n = wn * 64 + ni * 8 + g;
                bf[ni][0] = Ks[n][kb + q];
                bf[ni][1] = Ks[n][kb + q + 4];
            }
#pragma unroll
            for (int mi = 0; mi < 2; mi++)
#pragma unroll
                for (int ni = 0; ni < 8; ni++) mma8(acc[mi][ni], a[mi], bf[ni]);
        }
        __syncthreads();
    }

    const float scale = 0.03125f;
#pragma unroll
    for (int mi = 0; mi < 2; mi++) {
        int r0 = i0 + wm * 32 + mi * 16 + g;
#pragma unroll
        for (int ni = 0; ni < 8; ni++) {
            int c = j0 + wn * 64 + ni * 8 + q * 2;
            size_t a0 = ((size_t)bh * N_ + r0) * N_ + c;
            size_t a1 = ((size_t)bh * N_ + r0 + 8) * N_ + c;
            *(float2*)(attn + a0) =
                make_float2(acc[mi][ni][0] * scale, acc[mi][ni][1] * scale);
            *(float2*)(attn + a1) =
                make_float2(acc[mi][ni][2] * scale, acc[mi][ni][3] * scale);
        }
    }
}

// ---------------- row softmax over N=1024 ----------------------------------
__global__ void __launch_bounds__(256) softmax_kernel(float* __restrict__ attn)
{
    __shared__ float red[8];
    size_t row = blockIdx.x;
    float* p = attn + row * N_;
    int t = threadIdx.x;
    float v[4];
    float mx = -1e30f;
#pragma unroll
    for (int i = 0; i < 4; i++) { v[i] = p[t + i * 256]; mx = fmaxf(mx, v[i]); }
#pragma unroll
    for (int off = 16; off > 0; off >>= 1)
        mx = fmaxf(mx, __shfl_xor_sync(0xffffffffu, mx, off));
    if ((t & 31) == 0) red[t >> 5] = mx;
    __syncthreads();
    mx = red[0];
#pragma unroll
    for (int i = 1; i < 8; i++) mx = fmaxf(mx, red[i]);
    __syncthreads();
    float sum = 0.f;
#pragma unroll
    for (int i = 0; i < 4; i++) { v[i] = __expf(v[i] - mx); sum += v[i]; }
#pragma unroll
    for (int off = 16; off > 0; off >>= 1)
        sum += __shfl_xor_sync(0xffffffffu, sum, off);
    if ((t & 31) == 0) red[t >> 5] = sum;
    __syncthreads();
    sum = 0.f;
#pragma unroll
    for (int i = 0; i < 8; i++) sum += red[i];
    float inv = 1.f / sum;
#pragma unroll
    for (int i = 0; i < 4; i++) p[t + i * 256] = v[i] * inv;
}

// ---------------- O = attn @ V (tf32 TC), output [b, n, h*dh] --------------
__global__ void __launch_bounds__(256) av_tc(
    const float* __restrict__ attn, const float* __restrict__ qkv,
    float* __restrict__ o)
{
    __shared__ float As_[128][36];
    __shared__ float Vs[32][68];
    int bh = blockIdx.y;
    int b = bh >> 4, h = bh & 15;
    int i0 = blockIdx.x * 128;
    const float* Ab = attn + ((size_t)bh * N_ + i0) * N_;
    const float* Vb = qkv + (size_t)b * N_ * 3 * D_ + 2 * D_ + (size_t)h * DH_;
    int tid = threadIdx.x;
    int w = tid >> 5, lane = tid & 31;
    int wm = w >> 1, wn = w & 1;
    int g = lane >> 2, q = lane & 3;

    float acc[2][4][4];
#pragma unroll
    for (int mi = 0; mi < 2; mi++)
#pragma unroll
        for (int ni = 0; ni < 4; ni++)
#pragma unroll
            for (int k = 0; k < 4; k++) acc[mi][ni][k] = 0.f;

    for (int k0 = 0; k0 < N_; k0 += 32) {
#pragma unroll
        for (int i = 0; i < 4; i++) {
            int idx = tid + i * 256;
            int r = idx >> 3, c4 = (idx & 7) * 4;
            float4 f = *(const float4*)(Ab + (size_t)r * N_ + k0 + c4);
            f.x = f2tf(f.x); f.y = f2tf(f.y); f.z = f2tf(f.z); f.w = f2tf(f.w);
            *(float4*)&As_[r][c4] = f;
        }
#pragma unroll
        for (int i = 0; i < 2; i++) {
            int idx = tid + i * 256;
            int r = idx >> 4, c4 = (idx & 15) * 4;
            float4 f = *(const float4*)(Vb + (size_t)(k0 + r) * 3 * D_ + c4);
            f.x = f2tf(f.x); f.y = f2tf(f.y); f.z = f2tf(f.z); f.w = f2tf(f.w);
            *(float4*)&Vs[r][c4] = f;
        }
        __syncthreads();
#pragma unroll
        for (int ks = 0; ks < 4; ks++) {
            int kb = ks * 8;
            float a[2][4];
#pragma unroll
            for (int mi = 0; mi < 2; mi++) {
                int m = wm * 32 + mi * 16;
                a[mi][0] = As_[m + g    ][kb + q];
                a[mi][1] = As_[m + g + 8][kb + q];
                a[mi][2] = As_[m + g    ][kb + q + 4];
                a[mi][3] = As_[m + g + 8][kb + q + 4];
            }
            float bf[4][2];
#pragma unroll
            for (int ni = 0; ni < 4; ni++) {
                int n = wn * 32 + ni * 8 + g;
                bf[ni][0] = Vs[kb + q    ][n];
                bf[ni][1] = Vs[kb + q + 4][n];
            }
#pragma unroll
            for (int mi = 0; mi < 2; mi++)
#pragma unroll
                for (int ni = 0; ni < 4; ni++) mma8(acc[mi][ni], a[mi], bf[ni]);
        }
        __syncthreads();
    }

#pragma unroll
    for (int mi = 0; mi < 2; mi++) {
        int r0 = i0 + wm * 32 + mi * 16 + g;
#pragma unroll
        for (int ni = 0; ni < 4; ni++) {
            int c = wn * 32 + ni * 8 + q * 2;
            size_t a0 = ((size_t)b * N_ + r0) * D_ + h * DH_ + c;
            size_t a1 = ((size_t)b * N_ + r0 + 8) * D_ + h * DH_ + c;
            *(float2*)(o + a0) = make_float2(acc[mi][ni][0], acc[mi][ni][1]);
            *(float2*)(o + a1) = make_float2(acc[mi][ni][2], acc[mi][ni][3]);
        }
    }
}

// ---------------- orchestration --------------------------------------------
#define SMEM_BN256 ((2 * 128 * 36 + 2 * 32 * 260) * 4)
#define SMEM_BN128 ((2 * 128 * 36 + 2 * 32 * 132) * 4)

extern "C" void kernel_launch(void* const* d_in, const int* in_sizes, int n_in,
                              void* d_out, int out_size)
{
    (void)in_sizes; (void)n_in; (void)out_size;
    const float* x     = (const float*)d_in[0];
    const float* ln1_s = (const float*)d_in[1];
    const float* ln1_b = (const float*)d_in[2];
    const float* w_qkv = (const float*)d_in[3];
    const float* w_out = (const float*)d_in[4];
    const float* b_out = (const float*)d_in[5];
    const float* ln2_s = (const float*)d_in[6];
    const float* ln2_b = (const float*)d_in[7];
    const float* w1    = (const float*)d_in[8];
    const float* b1    = (const float*)d_in[9];
    const float* w2    = (const float*)d_in[10];
    const float* b2    = (const float*)d_in[11];
    float* out = (float*)d_out;

    float *h, *qkv, *attn, *o, *mlp;
    cudaGetSymbolAddress((void**)&h,    g_h);
    cudaGetSymbolAddress((void**)&qkv,  g_qkv);
    cudaGetSymbolAddress((void**)&attn, g_attn);
    cudaGetSymbolAddress((void**)&o,    g_o);
    cudaGetSymbolAddress((void**)&mlp,  g_mlp);

    cudaFuncSetAttribute(gemm_tc<256, 64, 64, 0>,
        cudaFuncAttributeMaxDynamicSharedMemorySize, SMEM_BN256);
    cudaFuncSetAttribute(gemm_tc<256, 64, 64, 3>,
        cudaFuncAttributeMaxDynamicSharedMemorySize, SMEM_BN256);
    cudaFuncSetAttribute(gemm_tc<128, 32, 64, 5>,
        cudaFuncAttributeMaxDynamicSharedMemorySize, SMEM_BN128);

    cudaMemcpyAsync(out, x, (size_t)M_ * D_ * sizeof(float),
                    cudaMemcpyDeviceToDevice);

    for (int l = 0; l < DEPTH_; l++) {
        // --- attention block ---
        ln_kernel<<<M_, 256>>>(out, ln1_s + (size_t)l * D_, ln1_b + (size_t)l * D_, h);
        gemm_tc<256, 64, 64, 0><<<dim3(3 * D_ / 256, M_ / 128), 256, SMEM_BN256>>>(
            h, w_qkv + (size_t)l * D_ * 3 * D_, nullptr, nullptr,
            qkv, M_, 3 * D_, D_);
        scores_tc<<<dim3(8, 8, B_ * H_), 256>>>(qkv, attn);
        softmax_kernel<<<B_ * H_ * N_, 256>>>(attn);
        av_tc<<<dim3(8, B_ * H_), 256>>>(attn, qkv, o);
        gemm_tc<128, 32, 64, 5><<<dim3(D_ / 128, M_ / 128), 256, SMEM_BN128>>>(
            o, w_out + (size_t)l * D_ * D_, b_out + (size_t)l * D_,
            out, out, M_, D_, D_);
        // --- MLP block ---
        ln_kernel<<<M_, 256>>>(out, ln2_s + (size_t)l * D_, ln2_b + (size_t)l * D_, h);
        gemm_tc<256, 64, 64, 3><<<dim3(MLP_ / 256, M_ / 128), 256, SMEM_BN256>>>(
            h, w1 + (size_t)l * D_ * MLP_, b1 + (size_t)l * MLP_,
            nullptr, mlp, M_, MLP_, D_);
        gemm_tc<128, 32, 64, 5><<<dim3(D_ / 128, M_ / 128), 256, SMEM_BN128>>>(
            mlp, w2 + (size_t)l * MLP_ * D_, b2 + (size_t)l * D_,
            out, out, M_, D_, MLP_);
    }
}